// round 3
// baseline (speedup 1.0000x reference)
#include <cuda_runtime.h>
#include <math.h>

// Problem constants (fixed shapes per reference)
#define NN 98304      // total nodes = B * ACT
#define CC 64         // channels
#define EE 1572864    // edges
#define HH 32         // hidden

// ---------------- static device scratch (no allocation allowed) --------------
__device__ int   g_cnt[NN];        // in-degree (excl. self loop)
__device__ float g_dinv[NN];       // rsqrt(deg+1)
__device__ int   g_rowptr[NN + 1]; // CSR offsets (by target/col)
__device__ int   g_pos[NN];        // scatter cursors
__device__ int   g_src[EE];        // CSR source-node indices
__device__ float g_xw[NN * CC];    // state @ W_gcn
__device__ float g_h[NN * CC];     // relu(gcn) + state
__device__ float g_sum;            // global softplus sum

// ---------------- kernels ----------------------------------------------------

__global__ void k_init() {
    int i = blockIdx.x * blockDim.x + threadIdx.x;
    if (i < NN) g_cnt[i] = 0;
    if (i == 0) g_sum = 0.0f;
}

__global__ void k_count(const int* __restrict__ col) {
    int e = blockIdx.x * blockDim.x + threadIdx.x;
    if (e < EE) atomicAdd(&g_cnt[col[e]], 1);
}

// Single-block exclusive scan over N=98304 counts (1024 threads x 96 chunk).
// Also emits dinv and initializes scatter cursors.
__global__ void k_scan() {
    __shared__ int tot[1024];
    const int CH = NN / 1024;   // 96 exactly
    int t = threadIdx.x;
    int base = t * CH;
    int s = 0;
    #pragma unroll 4
    for (int i = 0; i < CH; i++) s += g_cnt[base + i];
    tot[t] = s;
    __syncthreads();
    // Hillis-Steele inclusive scan
    for (int off = 1; off < 1024; off <<= 1) {
        int v = tot[t];
        int a = (t >= off) ? tot[t - off] : 0;
        __syncthreads();
        tot[t] = v + a;
        __syncthreads();
    }
    int run = (t == 0) ? 0 : tot[t - 1];
    for (int i = 0; i < CH; i++) {
        int idx = base + i;
        int c = g_cnt[idx];
        g_rowptr[idx] = run;
        g_pos[idx]    = run;
        g_dinv[idx]   = rsqrtf((float)(c + 1));
        run += c;
    }
    if (t == 1023) g_rowptr[NN] = run;
}

__global__ void k_scatter(const int* __restrict__ row, const int* __restrict__ col) {
    int e = blockIdx.x * blockDim.x + threadIdx.x;
    if (e < EE) {
        int c = col[e];
        int idx = atomicAdd(&g_pos[c], 1);
        g_src[idx] = row[e];
    }
}

// xw = state @ W_gcn ; warp-per-node, W in SMEM, row held in 2 regs/lane.
__global__ void k_xw(const float* __restrict__ state, const float* __restrict__ Wg) {
    __shared__ float Ws[CC * CC];   // 16 KB
    int t = threadIdx.x;
    for (int i = t; i < CC * CC; i += blockDim.x) Ws[i] = Wg[i];
    __syncthreads();
    int lane = t & 31;
    int n = blockIdx.x * (blockDim.x >> 5) + (t >> 5);
    float x0 = state[n * CC + lane];
    float x1 = state[n * CC + 32 + lane];
    float a0 = 0.f, a1 = 0.f;
    #pragma unroll
    for (int k = 0; k < 32; k++) {
        float v = __shfl_sync(0xffffffffu, x0, k);
        a0 += v * Ws[k * CC + lane];
        a1 += v * Ws[k * CC + 32 + lane];
    }
    #pragma unroll
    for (int k = 0; k < 32; k++) {
        float v = __shfl_sync(0xffffffffu, x1, k);
        a0 += v * Ws[(k + 32) * CC + lane];
        a1 += v * Ws[(k + 32) * CC + 32 + lane];
    }
    g_xw[n * CC + lane]      = a0;
    g_xw[n * CC + 32 + lane] = a1;
}

// Pull-style aggregation + GCN epilogue. Warp per node, no atomics.
// Lane l handles channels 2l and 2l+1 via one float2 (LDG.64) per edge.
// Unroll-by-4 with hoisted src/dinv loads -> ~8 independent loads in flight.
// out[n] = relu( dinv[n]*( sum_e dinv[src]*xw[src] + dinv[n]*xw[n] ) + b ) + state[n]
__global__ void k_gather(const float* __restrict__ state, const float* __restrict__ b_gcn) {
    int t = threadIdx.x;
    int lane = t & 31;
    int n = blockIdx.x * (blockDim.x >> 5) + (t >> 5);
    int j   = g_rowptr[n];
    int end = g_rowptr[n + 1];
    const float2* xw2 = (const float2*)g_xw;
    int c2 = lane;                   // float2 index within a 32-float2 row
    float acc0 = 0.f, acc1 = 0.f;

    for (; j + 4 <= end; j += 4) {
        int sA = g_src[j];
        int sB = g_src[j + 1];
        int sC = g_src[j + 2];
        int sD = g_src[j + 3];
        float wA = g_dinv[sA];
        float wB = g_dinv[sB];
        float wC = g_dinv[sC];
        float wD = g_dinv[sD];
        float2 vA = xw2[sA * 32 + c2];
        float2 vB = xw2[sB * 32 + c2];
        float2 vC = xw2[sC * 32 + c2];
        float2 vD = xw2[sD * 32 + c2];
        acc0 += wA * vA.x + wB * vB.x + wC * vC.x + wD * vD.x;
        acc1 += wA * vA.y + wB * vB.y + wC * vC.y + wD * vD.y;
    }
    for (; j < end; j++) {
        int s = g_src[j];
        float w = g_dinv[s];
        float2 v = xw2[s * 32 + c2];
        acc0 += w * v.x;
        acc1 += w * v.y;
    }

    float dn = g_dinv[n];
    float2 self = xw2[n * 32 + c2];
    const float2* b2v = (const float2*)b_gcn;
    const float2* st2 = (const float2*)state;
    float2 b  = b2v[c2];
    float2 st = st2[n * 32 + c2];
    float o0 = dn * (acc0 + dn * self.x) + b.x;
    float o1 = dn * (acc1 + dn * self.y) + b.y;
    o0 = fmaxf(o0, 0.f) + st.x;
    o1 = fmaxf(o1, 0.f) + st.y;
    float2 o; o.x = o0; o.y = o1;
    ((float2*)g_h)[n * 32 + c2] = o;
}

// Fused MLP 64->32->32->1 + softplus; writes conc to out, block-reduced sum.
__global__ void k_mlp(const float* __restrict__ W1, const float* __restrict__ b1,
                      const float* __restrict__ W2, const float* __restrict__ b2,
                      const float* __restrict__ W3, const float* __restrict__ b3,
                      float* __restrict__ out) {
    __shared__ float W1s[CC * HH];   // 8 KB
    __shared__ float W2s[HH * HH];   // 4 KB
    __shared__ float W3s[HH], b1s[HH], b2s[HH];
    __shared__ float b3s;
    __shared__ float wsum[4];
    int t = threadIdx.x;
    for (int i = t; i < CC * HH; i += 128) W1s[i] = W1[i];
    for (int i = t; i < HH * HH; i += 128) W2s[i] = W2[i];
    if (t < HH) { W3s[t] = W3[t]; b1s[t] = b1[t]; b2s[t] = b2[t]; }
    if (t == 0) b3s = b3[0];
    __syncthreads();

    int lane = t & 31, warp = t >> 5;
    int gw = blockIdx.x * 4 + warp;
    int nwarps = gridDim.x * 4;
    float lsum = 0.f;

    for (int n = gw; n < NN; n += nwarps) {
        float x0 = g_h[n * CC + lane];
        float x1 = g_h[n * CC + 32 + lane];
        float a1 = b1s[lane];
        #pragma unroll
        for (int k = 0; k < 32; k++)
            a1 += __shfl_sync(0xffffffffu, x0, k) * W1s[k * HH + lane];
        #pragma unroll
        for (int k = 0; k < 32; k++)
            a1 += __shfl_sync(0xffffffffu, x1, k) * W1s[(k + 32) * HH + lane];
        a1 = (a1 > 0.f) ? a1 : 0.01f * a1;

        float a2 = b2s[lane];
        #pragma unroll
        for (int k = 0; k < 32; k++)
            a2 += __shfl_sync(0xffffffffu, a1, k) * W2s[k * HH + lane];
        a2 = (a2 > 0.f) ? a2 : 0.01f * a2;

        float p = a2 * W3s[lane];
        #pragma unroll
        for (int o = 16; o > 0; o >>= 1) p += __shfl_xor_sync(0xffffffffu, p, o);

        if (lane == 0) {
            float z = p + b3s;
            // numerically stable softplus
            float sp = fmaxf(z, 0.f) + log1pf(expf(-fabsf(z)));
            out[n] = sp;
            lsum += sp;
        }
    }
    if (lane == 0) wsum[warp] = lsum;
    __syncthreads();
    if (t == 0) atomicAdd(&g_sum, wsum[0] + wsum[1] + wsum[2] + wsum[3]);
}

__global__ void k_norm(float* __restrict__ out) {
    int i = blockIdx.x * blockDim.x + threadIdx.x;
    if (i < NN) out[i] = out[i] / (g_sum + 1e-20f);
}

// ---------------- launch ------------------------------------------------------

extern "C" void kernel_launch(void* const* d_in, const int* in_sizes, int n_in,
                              void* d_out, int out_size) {
    const float* state = (const float*)d_in[0];
    const int*   ei    = (const int*)  d_in[1];   // [2, E]
    const float* Wg    = (const float*)d_in[2];
    const float* bg    = (const float*)d_in[3];
    const float* W1    = (const float*)d_in[4];
    const float* b1    = (const float*)d_in[5];
    const float* W2    = (const float*)d_in[6];
    const float* b2    = (const float*)d_in[7];
    const float* W3    = (const float*)d_in[8];
    const float* b3    = (const float*)d_in[9];
    float* out = (float*)d_out;

    const int* row = ei;        // sources
    const int* col = ei + EE;   // targets

    k_init   <<<NN / 256, 256>>>();
    k_count  <<<EE / 256, 256>>>(col);
    k_xw     <<<NN / 8,   256>>>(state, Wg);     // 8 warps/block, warp-per-node
    k_scan   <<<1, 1024>>>();
    k_scatter<<<EE / 256, 256>>>(row, col);
    k_gather <<<NN / 8,   256>>>(state, bg);
    k_mlp    <<<592, 128>>>(W1, b1, W2, b2, W3, b3, out);
    k_norm   <<<NN / 256, 256>>>(out);
}

// round 7
// speedup vs baseline: 2.4912x; 2.4912x over previous
#include <cuda_runtime.h>
#include <math.h>

// Problem constants (fixed shapes per reference)
#define NN 98304      // total nodes = B * ACT
#define CC 64         // channels
#define EE 1572864    // edges
#define HH 32         // hidden
#define SCAN_BLKS 96  // NN / 1024

// ---------------- static device scratch (no allocation allowed) --------------
__device__ int   g_cnt[NN];        // in-degree (excl. self loop)
__device__ float g_dinv[NN];       // rsqrt(deg+1)
__device__ int   g_rowptr[NN + 1]; // CSR offsets (by target/col)
__device__ int   g_pos[NN];        // scatter cursors
__device__ int   g_src[EE];        // CSR source-node indices
__device__ int   g_btot[SCAN_BLKS];// per-block totals
__device__ int   g_boff[SCAN_BLKS];// per-block exclusive offsets
__device__ float g_xw[NN * CC];    // state @ W_gcn
__device__ float g_h[NN * CC];     // relu(gcn) + state
__device__ float g_sum;            // global softplus sum

// ---------------- kernels ----------------------------------------------------

__global__ void k_init() {
    int i = blockIdx.x * blockDim.x + threadIdx.x;
    if (i < NN) g_cnt[i] = 0;
    if (i == 0) { g_sum = 0.0f; g_rowptr[NN] = EE; }
}

// 4 edges per thread via one int4 load; atomicAdd w/o return -> REDG.
__global__ void k_count(const int4* __restrict__ col4) {
    int e = blockIdx.x * blockDim.x + threadIdx.x;
    if (e < EE / 4) {
        int4 c = col4[e];
        atomicAdd(&g_cnt[c.x], 1);
        atomicAdd(&g_cnt[c.y], 1);
        atomicAdd(&g_cnt[c.z], 1);
        atomicAdd(&g_cnt[c.w], 1);
    }
}

// Phase 1: per-block exclusive scan (1024 elems/block), block totals, dinv.
__global__ void k_scan1() {
    __shared__ int wsum[32];
    int t = threadIdx.x;
    int lane = t & 31, warp = t >> 5;
    int i = blockIdx.x * 1024 + t;
    int c = g_cnt[i];
    // inclusive warp scan
    int x = c;
    #pragma unroll
    for (int off = 1; off < 32; off <<= 1) {
        int y = __shfl_up_sync(0xffffffffu, x, off);
        if (lane >= off) x += y;
    }
    if (lane == 31) wsum[warp] = x;
    __syncthreads();
    if (warp == 0) {
        int s = wsum[lane];
        #pragma unroll
        for (int off = 1; off < 32; off <<= 1) {
            int y = __shfl_up_sync(0xffffffffu, s, off);
            if (lane >= off) s += y;
        }
        wsum[lane] = s;   // inclusive over warps
    }
    __syncthreads();
    int excl = x - c + (warp > 0 ? wsum[warp - 1] : 0);
    g_rowptr[i] = excl;                       // block-local for now
    g_dinv[i]   = rsqrtf((float)(c + 1));
    if (t == 1023) g_btot[blockIdx.x] = excl + c;
}

// Phase 2: single small block scans the 96 block totals -> exclusive offsets.
__global__ void k_scan2() {
    __shared__ int s[128];
    int t = threadIdx.x;
    int v = (t < SCAN_BLKS) ? g_btot[t] : 0;
    s[t] = v;
    __syncthreads();
    for (int off = 1; off < 128; off <<= 1) {
        int a = (t >= off) ? s[t - off] : 0;
        __syncthreads();
        s[t] += a;
        __syncthreads();
    }
    if (t < SCAN_BLKS) g_boff[t] = s[t] - v;  // exclusive
}

// Phase 3: add block offsets, init cursors.
__global__ void k_scan3() {
    int i = blockIdx.x * 1024 + threadIdx.x;
    int v = g_rowptr[i] + g_boff[blockIdx.x];
    g_rowptr[i] = v;
    g_pos[i]    = v;
}

// 4 edges per thread; int4 loads of row+col halve edge-list LDG traffic.
__global__ void k_scatter(const int4* __restrict__ row4, const int4* __restrict__ col4) {
    int e = blockIdx.x * blockDim.x + threadIdx.x;
    if (e < EE / 4) {
        int4 r = row4[e];
        int4 c = col4[e];
        g_src[atomicAdd(&g_pos[c.x], 1)] = r.x;
        g_src[atomicAdd(&g_pos[c.y], 1)] = r.y;
        g_src[atomicAdd(&g_pos[c.z], 1)] = r.z;
        g_src[atomicAdd(&g_pos[c.w], 1)] = r.w;
    }
}

// xw = state @ W_gcn ; warp-per-node, W in SMEM, row held in 2 regs/lane.
__global__ void k_xw(const float* __restrict__ state, const float* __restrict__ Wg) {
    __shared__ float Ws[CC * CC];   // 16 KB
    int t = threadIdx.x;
    for (int i = t; i < CC * CC; i += blockDim.x) Ws[i] = Wg[i];
    __syncthreads();
    int lane = t & 31;
    int n = blockIdx.x * (blockDim.x >> 5) + (t >> 5);
    float x0 = state[n * CC + lane];
    float x1 = state[n * CC + 32 + lane];
    float a0 = 0.f, a1 = 0.f;
    #pragma unroll
    for (int k = 0; k < 32; k++) {
        float v = __shfl_sync(0xffffffffu, x0, k);
        a0 += v * Ws[k * CC + lane];
        a1 += v * Ws[k * CC + 32 + lane];
    }
    #pragma unroll
    for (int k = 0; k < 32; k++) {
        float v = __shfl_sync(0xffffffffu, x1, k);
        a0 += v * Ws[(k + 32) * CC + lane];
        a1 += v * Ws[(k + 32) * CC + 32 + lane];
    }
    g_xw[n * CC + lane]      = a0;
    g_xw[n * CC + 32 + lane] = a1;
}

// Pull-style aggregation + GCN epilogue. Warp per node, no atomics.
// Lane l handles channels 2l and 2l+1 via one float2 (LDG.64) per edge.
// Unroll-by-4 with hoisted src/dinv loads -> ~8 independent loads in flight.
__global__ void k_gather(const float* __restrict__ state, const float* __restrict__ b_gcn) {
    int t = threadIdx.x;
    int lane = t & 31;
    int n = blockIdx.x * (blockDim.x >> 5) + (t >> 5);
    int j   = g_rowptr[n];
    int end = g_rowptr[n + 1];
    const float2* xw2 = (const float2*)g_xw;
    int c2 = lane;                   // float2 index within a 32-float2 row
    float acc0 = 0.f, acc1 = 0.f;

    for (; j + 4 <= end; j += 4) {
        int sA = g_src[j];
        int sB = g_src[j + 1];
        int sC = g_src[j + 2];
        int sD = g_src[j + 3];
        float wA = g_dinv[sA];
        float wB = g_dinv[sB];
        float wC = g_dinv[sC];
        float wD = g_dinv[sD];
        float2 vA = xw2[sA * 32 + c2];
        float2 vB = xw2[sB * 32 + c2];
        float2 vC = xw2[sC * 32 + c2];
        float2 vD = xw2[sD * 32 + c2];
        acc0 += wA * vA.x + wB * vB.x + wC * vC.x + wD * vD.x;
        acc1 += wA * vA.y + wB * vB.y + wC * vC.y + wD * vD.y;
    }
    for (; j < end; j++) {
        int s = g_src[j];
        float w = g_dinv[s];
        float2 v = xw2[s * 32 + c2];
        acc0 += w * v.x;
        acc1 += w * v.y;
    }

    float dn = g_dinv[n];
    float2 self = xw2[n * 32 + c2];
    const float2* b2v = (const float2*)b_gcn;
    const float2* st2 = (const float2*)state;
    float2 b  = b2v[c2];
    float2 st = st2[n * 32 + c2];
    float o0 = dn * (acc0 + dn * self.x) + b.x;
    float o1 = dn * (acc1 + dn * self.y) + b.y;
    o0 = fmaxf(o0, 0.f) + st.x;
    o1 = fmaxf(o1, 0.f) + st.y;
    float2 o; o.x = o0; o.y = o1;
    ((float2*)g_h)[n * 32 + c2] = o;
}

// Fused MLP 64->32->32->1 + softplus; writes conc to out, block-reduced sum.
__global__ void k_mlp(const float* __restrict__ W1, const float* __restrict__ b1,
                      const float* __restrict__ W2, const float* __restrict__ b2,
                      const float* __restrict__ W3, const float* __restrict__ b3,
                      float* __restrict__ out) {
    __shared__ float W1s[CC * HH];   // 8 KB
    __shared__ float W2s[HH * HH];   // 4 KB
    __shared__ float W3s[HH], b1s[HH], b2s[HH];
    __shared__ float b3s;
    __shared__ float wsum[4];
    int t = threadIdx.x;
    for (int i = t; i < CC * HH; i += 128) W1s[i] = W1[i];
    for (int i = t; i < HH * HH; i += 128) W2s[i] = W2[i];
    if (t < HH) { W3s[t] = W3[t]; b1s[t] = b1[t]; b2s[t] = b2[t]; }
    if (t == 0) b3s = b3[0];
    __syncthreads();

    int lane = t & 31, warp = t >> 5;
    int gw = blockIdx.x * 4 + warp;
    int nwarps = gridDim.x * 4;
    float lsum = 0.f;

    for (int n = gw; n < NN; n += nwarps) {
        float x0 = g_h[n * CC + lane];
        float x1 = g_h[n * CC + 32 + lane];
        float a1 = b1s[lane];
        #pragma unroll
        for (int k = 0; k < 32; k++)
            a1 += __shfl_sync(0xffffffffu, x0, k) * W1s[k * HH + lane];
        #pragma unroll
        for (int k = 0; k < 32; k++)
            a1 += __shfl_sync(0xffffffffu, x1, k) * W1s[(k + 32) * HH + lane];
        a1 = (a1 > 0.f) ? a1 : 0.01f * a1;

        float a2 = b2s[lane];
        #pragma unroll
        for (int k = 0; k < 32; k++)
            a2 += __shfl_sync(0xffffffffu, a1, k) * W2s[k * HH + lane];
        a2 = (a2 > 0.f) ? a2 : 0.01f * a2;

        float p = a2 * W3s[lane];
        #pragma unroll
        for (int o = 16; o > 0; o >>= 1) p += __shfl_xor_sync(0xffffffffu, p, o);

        if (lane == 0) {
            float z = p + b3s;
            // numerically stable softplus
            float sp = fmaxf(z, 0.f) + log1pf(expf(-fabsf(z)));
            out[n] = sp;
            lsum += sp;
        }
    }
    if (lane == 0) wsum[warp] = lsum;
    __syncthreads();
    if (t == 0) atomicAdd(&g_sum, wsum[0] + wsum[1] + wsum[2] + wsum[3]);
}

__global__ void k_norm(float* __restrict__ out) {
    int i = blockIdx.x * blockDim.x + threadIdx.x;
    if (i < NN) {
        float r = __frcp_rn(g_sum + 1e-20f);
        out[i] = out[i] * r;
    }
}

// ---------------- launch ------------------------------------------------------

extern "C" void kernel_launch(void* const* d_in, const int* in_sizes, int n_in,
                              void* d_out, int out_size) {
    const float* state = (const float*)d_in[0];
    const int*   ei    = (const int*)  d_in[1];   // [2, E]
    const float* Wg    = (const float*)d_in[2];
    const float* bg    = (const float*)d_in[3];
    const float* W1    = (const float*)d_in[4];
    const float* b1    = (const float*)d_in[5];
    const float* W2    = (const float*)d_in[6];
    const float* b2    = (const float*)d_in[7];
    const float* W3    = (const float*)d_in[8];
    const float* b3    = (const float*)d_in[9];
    float* out = (float*)d_out;

    const int* row = ei;        // sources
    const int* col = ei + EE;   // targets

    k_init   <<<NN / 256, 256>>>();
    k_count  <<<EE / 4 / 256, 256>>>((const int4*)col);
    k_xw     <<<NN / 8,   256>>>(state, Wg);     // 8 warps/block, warp-per-node
    k_scan1  <<<SCAN_BLKS, 1024>>>();
    k_scan2  <<<1, 128>>>();
    k_scan3  <<<SCAN_BLKS, 1024>>>();
    k_scatter<<<EE / 4 / 256, 256>>>((const int4*)row, (const int4*)col);
    k_gather <<<NN / 8,   256>>>(state, bg);
    k_mlp    <<<592, 128>>>(W1, b1, W2, b2, W3, b3, out);
    k_norm   <<<NN / 256, 256>>>(out);
}